// round 13
// baseline (speedup 1.0000x reference)
#include <cuda_runtime.h>
#include <cuda_fp16.h>

// Weighted 4D LUT interpolation with 4x spatial upscale.
// Shapes: L=4, D=17, S=4, B=4, H=256, W=256, BINSIZE=16.
// lut:    [4,17,17,17,17,4,4] f32  (d_in[0])
// weight: [4,4,256,256]       f32  (d_in[2])
// x:      [4,1,256,256]       f32  (d_in[3])
// out:    [4,1,1024,1024]     f32
//
// The kernel is pinned at the chip L2 (LTS) bandwidth cap; the only lever
// left is locality. All 5 simplex vertices of a pixel live in the 148KB LUT
// slab fixed by (base[0], base[1]), so we bin pixels by that pair (256 bins)
// and process one bin per 1024-thread block: every gather hits a region that
// fits in L1 (228KB), collapsing gather L2 traffic ~168MB -> ~40MB.
// Pipeline: relayout(fp16, line-packed) -> zero -> hist -> scan -> scatter
// -> main (4 lanes/pixel, LDG.256, HFMA2 k-sum, sort-network setup).

#define NPIX (4 * 256 * 256)
#define D4   83521          // 17^4

// [flat][s][l] fp16: 64 halves = 128B per flat value = 8 uint4.
__device__ __align__(256) uint4 g_lut2h[(size_t)D4 * 8];
__device__ unsigned g_hist[256];
__device__ unsigned g_start[256];
__device__ unsigned g_cursor[256];
__device__ unsigned g_list[NPIX];

__device__ __forceinline__ void ldg256(uint4& a, uint4& b, const void* p)
{
    asm("ld.global.nc.v8.b32 {%0,%1,%2,%3,%4,%5,%6,%7}, [%8];"
        : "=r"(a.x), "=r"(a.y), "=r"(a.z), "=r"(a.w),
          "=r"(b.x), "=r"(b.y), "=r"(b.z), "=r"(b.w)
        : "l"(p));
}

__device__ __forceinline__ int pixel_bin(const float* __restrict__ x, int g)
{
    int w = g & 255, h = (g >> 8) & 255, b = g >> 16;
    int w1 = (w + 1 < 256) ? w + 1 : 254;
    const float* xb = x + b * 65536;
    float p0 = __ldg(xb + h * 256 + w);
    float p1 = __ldg(xb + h * 256 + w1);
    int b0 = min(max((int)floorf(p0 * (1.0f / 16.0f)), 0), 15);
    int b1 = min(max((int)floorf(p1 * (1.0f / 16.0f)), 0), 15);
    return b0 * 16 + b1;
}

__global__ void __launch_bounds__(256) relayout_kernel(const float* __restrict__ lut)
{
    int t = blockIdx.x * 256 + threadIdx.x;   // one dst uint4 per thread
    if (t >= D4 * 8) return;
    int j    = t & 7;          // s-pair index (s = 2j, 2j+1)
    int flat = t >> 3;

    float2 fl[4];
#pragma unroll
    for (int l = 0; l < 4; ++l)
        fl[l] = __ldg((const float2*)(lut + ((size_t)l * D4 + flat) * 16 + 2 * j));

    __half2 hh[4];
    hh[0] = __floats2half2_rn(fl[0].x, fl[1].x);   // s(2j):   l0,l1
    hh[1] = __floats2half2_rn(fl[2].x, fl[3].x);   // s(2j):   l2,l3
    hh[2] = __floats2half2_rn(fl[0].y, fl[1].y);   // s(2j+1): l0,l1
    hh[3] = __floats2half2_rn(fl[2].y, fl[3].y);   // s(2j+1): l2,l3

    g_lut2h[(size_t)flat * 8 + j] = *reinterpret_cast<uint4*>(hh);
}

__global__ void zero_kernel()
{
    g_hist[threadIdx.x] = 0;
}

__global__ void __launch_bounds__(1024) hist_kernel(const float* __restrict__ x)
{
    __shared__ unsigned sh[256];
    int tid = threadIdx.x;
    if (tid < 256) sh[tid] = 0;
    __syncthreads();
    int g = blockIdx.x * 1024 + tid;
    int bin = pixel_bin(x, g);
    atomicAdd(&sh[bin], 1u);
    __syncthreads();
    if (tid < 256 && sh[tid]) atomicAdd(&g_hist[tid], sh[tid]);
}

__global__ void scan_kernel()
{
    __shared__ unsigned s[256];
    int t = threadIdx.x;
    unsigned mine = g_hist[t];
    s[t] = mine;
    __syncthreads();
#pragma unroll
    for (int o = 1; o < 256; o <<= 1) {
        unsigned v = (t >= o) ? s[t - o] : 0u;
        __syncthreads();
        s[t] += v;
        __syncthreads();
    }
    unsigned excl = s[t] - mine;
    g_start[t]  = excl;
    g_cursor[t] = excl;
}

__global__ void __launch_bounds__(1024) scatter_kernel(const float* __restrict__ x)
{
    __shared__ unsigned sh[256];
    __shared__ unsigned sbase[256];
    int tid = threadIdx.x;
    if (tid < 256) sh[tid] = 0;
    __syncthreads();
    int g = blockIdx.x * 1024 + tid;
    int bin = pixel_bin(x, g);
    unsigned r = atomicAdd(&sh[bin], 1u);
    __syncthreads();
    if (tid < 256 && sh[tid]) sbase[tid] = atomicAdd(&g_cursor[tid], sh[tid]);
    __syncthreads();
    g_list[sbase[bin] + r] = (unsigned)g;
}

__global__ void __launch_bounds__(1024) w4dlut_kernel(
    const float* __restrict__ weight,
    const float* __restrict__ x,
    float* __restrict__ out)
{
    int bin = blockIdx.x;                 // this block's (b0,b1) bin
    unsigned start = g_start[bin];
    unsigned count = g_hist[bin];

    int tid  = threadIdx.x;
    int q    = tid & 3;                   // lane within quad; output row sy=q
    int slot = tid >> 2;                  // 256 pixel slots per iteration

    for (unsigned i = slot; i < count; i += 256) {
        int g = (int)__ldg(&g_list[start + i]);
        int w = g & 255;
        int h = (g >> 8) & 255;
        int b = g >> 16;

        // ---- weight loads ----
        const float* wp = weight + ((size_t)b * 4 * 65536) + h * 256 + w;
        float wg0 = __ldg(wp);
        float wg1 = __ldg(wp + 65536);
        float wg2 = __ldg(wp + 2 * 65536);
        float wg3 = __ldg(wp + 3 * 65536);

        // ---- per-pixel scalar setup ----
        int h1 = (h + 1 < 256) ? h + 1 : 254;   // reflect pad
        int w1 = (w + 1 < 256) ? w + 1 : 254;

        const float* xb = x + b * 65536;
        float pv[4];
        pv[0] = __ldg(xb + h  * 256 + w );
        pv[1] = __ldg(xb + h  * 256 + w1);
        pv[2] = __ldg(xb + h1 * 256 + w );
        pv[3] = __ldg(xb + h1 * 256 + w1);

        float f[4];
        int   st[4] = {4913, 289, 17, 1};
        int   flat;
        {
            int base[4];
#pragma unroll
            for (int d = 0; d < 4; ++d) {
                float tt = pv[d] * (1.0f / 16.0f);
                float bf = floorf(tt);
                f[d] = tt - bf;
                int bi = (int)bf;
                bi = min(max(bi, 0), 15);
                base[d] = bi;
            }
            flat = ((base[0] * 17 + base[1]) * 17 + base[2]) * 17 + base[3];
        }

        // descending sort of (f, st): 5-exchange network (ties value-safe)
#define CSWAP(i, j)                                   \
        {                                             \
            bool sw = f[i] < f[j];                    \
            float ft = sw ? f[j] : f[i];              \
            f[j] = sw ? f[i] : f[j];                  \
            f[i] = ft;                                \
            int  it = sw ? st[j] : st[i];             \
            st[j] = sw ? st[i] : st[j];               \
            st[i] = it;                               \
        }
        CSWAP(0, 1) CSWAP(2, 3) CSWAP(0, 2) CSWAP(1, 3) CSWAP(1, 2)
#undef CSWAP

        float wts[5];
        wts[0] = 1.0f - f[0];
        wts[1] = f[0] - f[1];
        wts[2] = f[1] - f[2];
        wts[3] = f[2] - f[3];
        wts[4] = f[3];

        // ---- gathers: one LDG.256 per vertex (L1-resident 148KB region) ----
        const char* lbase = (const char*)g_lut2h + q * 32;
        unsigned    off   = (unsigned)flat * 128u;

        uint4   v0[5], v1[5];
        __half2 cc[5];
#pragma unroll
        for (int k = 0; k < 5; ++k) {
            if (k) off += (unsigned)st[k - 1] * 128u;
            cc[k] = __float2half2_rn(wts[k]);
            ldg256(v0[k], v1[k], lbase + off);
        }

        // ---- fp16 k-sum: 8 half2 accumulators ----
        __half2 acc[8];
#pragma unroll
        for (int i2 = 0; i2 < 8; ++i2) acc[i2] = __half2half2(__ushort_as_half(0));

#pragma unroll
        for (int k = 0; k < 5; ++k) {
            const __half2* ha = reinterpret_cast<const __half2*>(&v0[k]);
            const __half2* hb = reinterpret_cast<const __half2*>(&v1[k]);
            __half2 c = cc[k];
#pragma unroll
            for (int i2 = 0; i2 < 4; ++i2) {
                acc[i2]     = __hfma2(c, ha[i2], acc[i2]);
                acc[4 + i2] = __hfma2(c, hb[i2], acc[4 + i2]);
            }
        }

        // ---- fp32 epilogue ----
        float o[4];
#pragma unroll
        for (int i2 = 0; i2 < 4; ++i2) {
            float2 f01 = __half22float2(acc[2 * i2]);
            float2 f23 = __half22float2(acc[2 * i2 + 1]);
            float v = f01.x * wg0;
            v = fmaf(f01.y, wg1, v);
            v = fmaf(f23.x, wg2, v);
            v = fmaf(f23.y, wg3, v);
            o[i2] = v;
        }

        float4* op = (float4*)(out + (((size_t)b * 1024 + h * 4 + q) * 1024 + w * 4));
        *op = make_float4(o[0], o[1], o[2], o[3]);
    }
}

extern "C" void kernel_launch(void* const* d_in, const int* in_sizes, int n_in,
                              void* d_out, int out_size)
{
    const float* lut    = (const float*)d_in[0];
    const float* weight = (const float*)d_in[2];
    const float* x      = (const float*)d_in[3];
    float* out          = (float*)d_out;

    relayout_kernel<<<(D4 * 8 + 255) / 256, 256>>>(lut);
    zero_kernel<<<1, 256>>>();
    hist_kernel<<<NPIX / 1024, 1024>>>(x);
    scan_kernel<<<1, 256>>>();
    scatter_kernel<<<NPIX / 1024, 1024>>>(x);
    w4dlut_kernel<<<256, 1024>>>(weight, x, out);
}